// round 10
// baseline (speedup 1.0000x reference)
#include <cuda_runtime.h>
#include <math.h>

#define NB 16
#define HW 512
#define NPIX (NB*HW*HW)
#define LCAP 768
#define K4CTAS (NB*LCAP/32)   // 384
#define NPART 2048            // kmain CTAs
#define CTAS_PER_IMG 128

// ---------------- device scratch ----------------
__device__ float    g_bval[NB*4096];
__device__ int      g_bpos[NB*4096];
__device__ int      g_list[NB*LCAP];
__device__ int      g_cnt[NB];
__device__ double   g_pb[NPART];
__device__ double   g_pr[NPART];
__device__ double   g_pc[K4CTAS];
__device__ unsigned g_imgarr[NB];   // zero-init; reset after use
__device__ unsigned g_arrive;       // zero-init; reset after use

__device__ __forceinline__ int refl512(int i){ return i<0 ? -i : (i>511 ? 1022-i : i); }
__device__ __forceinline__ int clamp512(int i){ return i<0?0:(i>511?511:i); }

__device__ __forceinline__ void gw7(float* w){
  float e0=__expf(-4.5f), e1=__expf(-2.0f), e2=__expf(-0.5f);
  float s=1.0f+2.0f*(e0+e1+e2);
  w[0]=e0/s; w[1]=e1/s; w[2]=e2/s; w[3]=1.0f/s; w[4]=w[2]; w[5]=w[1]; w[6]=w[0];
}

__device__ __forceinline__ float fsqrt_pos(float z){
  return (z > 1e-37f) ? z*__frsqrt_rn(z) : 0.0f;
}

// smem layout (floats). Tile: 64 wide x 32 tall output.
#define OFF_SG  0       // gray: 44 rows x 76
#define OFF_SC  3344    // scores: 36 x 68
#define OFF_RS  5792    // row box sums: 36 x 64
#define OFF_P0  8096    // 42 x 76
#define OFF_P1  11288
#define OFF_P2  14480
#define OFF_T0  17672   // 42 x 68
#define OFF_T1  20528
#define OFF_T2  23384
#define OFF_RB  26240   // 32
#define OFF_RR  26272   // 32
#define BUFSZ   26304   // 105216 bytes

// ============ KMAIN ============
__global__ __launch_bounds__(1024,2) void kmain(const float* __restrict__ imgs,
                                                const float* __restrict__ scores){
  const int b = blockIdx.z;
  const int ty0 = blockIdx.y*32, tx0 = blockIdx.x*64;
  extern __shared__ __align__(16) float buf[];
  float* sg = buf + OFF_SG;
  float* sc = buf + OFF_SC;
  float* rs = buf + OFF_RS;
  float* p0 = buf + OFF_P0;
  float* p1 = buf + OFF_P1;
  float* p2 = buf + OFF_P2;
  float* t0 = buf + OFF_T0;
  float* t1 = buf + OFF_T1;
  float* t2 = buf + OFF_T2;
  float* rb = buf + OFF_RB;
  float* rr2= buf + OFF_RR;
  float* resp = buf + OFF_SG;   // 36x68, aliases sg (dead after B)
  float* rm   = buf + OFF_SC;   // 36x64, aliases sc
  float* sv   = buf + OFF_RS;   // 32x64, aliases rs

  const int ty = threadIdx.y, tx = threadIdx.x;
  const int tid = ty*32 + tx;
  const int lane = tid&31, wrp = tid>>5;
  const float NEG = __int_as_float(0xff800000u);
  const bool interior = (blockIdx.x-1u < 6u) && (blockIdx.y-1u < 14u);

  const float* rrp = imgs + (size_t)b*3*HW*HW;
  const float* ggp = rrp + HW*HW;
  const float* bbp = ggp + HW*HW;
  const float* sp  = scores + (size_t)b*HW*HW;

  // ---- loads: scores 36x68 and gray 44x76 ----
  if (interior){
    for (int iy=ty; iy<36; iy+=32){
      const float* r = sp + (ty0-2+iy)*HW + tx0-2;
      for (int ix=tx; ix<68; ix+=32) sc[iy*68+ix] = r[ix];
    }
    for (int iy=ty; iy<44; iy+=32){
      int o0 = (ty0-6+iy)*HW + tx0-6;
      for (int ix=tx; ix<76; ix+=32){
        int o=o0+ix;
        sg[iy*76+ix] = 0.299f*rrp[o] + 0.587f*ggp[o] + 0.114f*bbp[o];
      }
    }
  } else {
    for (int iy=ty; iy<36; iy+=32){
      int gy = refl512(ty0-2+iy);
      for (int ix=tx; ix<68; ix+=32) sc[iy*68+ix] = sp[gy*HW + refl512(tx0-2+ix)];
    }
    for (int iy=ty; iy<44; iy+=32){
      int gy = clamp512(ty0-6+iy);
      for (int ix=tx; ix<76; ix+=32){
        int o = gy*HW + clamp512(tx0-6+ix);
        sg[iy*76+ix] = 0.299f*rrp[o] + 0.587f*ggp[o] + 0.114f*bbp[o];
      }
    }
  }
  __syncthreads();

  // ---- phase0a: row sums of 5 (36 x 64) ----
  for (int iy=ty; iy<36; iy+=32){
    for (int ix=tx; ix<64; ix+=32){
      int base=iy*68+ix;
      rs[iy*64+ix] = sc[base]+sc[base+1]+sc[base+2]+sc[base+3]+sc[base+4];
    }
  }
  __syncthreads();

  // ---- phase0b: laplacian + reg + base bce ----
  {
    float v1=0.f, v2=0.f;
    const int oy=ty;
    #pragma unroll
    for (int t=0;t<2;t++){
      int ox = tx + 32*t;
      float S = rs[oy*64+ox]+rs[(oy+1)*64+ox]+rs[(oy+2)*64+ox]+rs[(oy+3)*64+ox]+rs[(oy+4)*64+ox];
      float p = sc[(oy+2)*68 + ox+2];
      float lap = (S - 25.0f*p) * (1.0f/48.0f);
      v2 += p * __expf(-lap);
      v1 += -fmaxf(__logf(1.0f-p), -100.0f);
    }
    #pragma unroll
    for (int off=16;off;off>>=1){
      v1 += __shfl_down_sync(0xffffffffu, v1, off);
      v2 += __shfl_down_sync(0xffffffffu, v2, off);
    }
    if (lane==0){ rb[wrp]=v1; rr2[wrp]=v2; }
  }
  __syncthreads();
  if (tid<32){
    float a1=rb[tid], a2=rr2[tid];
    #pragma unroll
    for (int off=16;off;off>>=1){
      a1 += __shfl_down_sync(0xffffffffu, a1, off);
      a2 += __shfl_down_sync(0xffffffffu, a2, off);
    }
    if (tid==0){
      int bid = (b*16 + blockIdx.y)*8 + blockIdx.x;
      g_pb[bid]=(double)a1; g_pr[bid]=(double)a2;
    }
  }

  // ---- B: gradient products, 42 x 74 ----
  if (interior){
    for (int iy=ty; iy<42; iy+=32){
      const float* c0 = &sg[ iy   *76];
      const float* c1 = &sg[(iy+1)*76];
      const float* c2 = &sg[(iy+2)*76];
      for (int ix=tx; ix<74; ix+=32){
        int lx = ix+1;
        float a=c0[lx-1], b_=c0[lx], c=c0[lx+1];
        float d=c1[lx-1],            e=c1[lx+1];
        float f=c2[lx-1], h=c2[lx],  k=c2[lx+1];
        float dx=(c-a+2.0f*(e-d)+k-f)*0.125f;
        float dy=(f-a+2.0f*(h-b_)+k-c)*0.125f;
        int o = iy*76+ix;
        p0[o]=dx*dx; p1[o]=dy*dy; p2[o]=dx*dy;
      }
    }
  } else {
    for (int iy=ty; iy<42; iy+=32){
      int qy = refl512(ty0-5+iy);
      int ly = qy - ty0 + 6;
      const float* c0 = &sg[(ly-1)*76];
      const float* c1 = &sg[ ly   *76];
      const float* c2 = &sg[(ly+1)*76];
      for (int ix=tx; ix<74; ix+=32){
        int qx = refl512(tx0-5+ix);
        int lx = qx - tx0 + 6;
        float a=c0[lx-1], b_=c0[lx], c=c0[lx+1];
        float d=c1[lx-1],            e=c1[lx+1];
        float f=c2[lx-1], h=c2[lx],  k=c2[lx+1];
        float dx=(c-a+2.0f*(e-d)+k-f)*0.125f;
        float dy=(f-a+2.0f*(h-b_)+k-c)*0.125f;
        int o = iy*76+ix;
        p0[o]=dx*dx; p1[o]=dy*dy; p2[o]=dx*dy;
      }
    }
  }
  __syncthreads();

  float w[7]; gw7(w);

  // ---- C: row blur, 42 rows x 34 x-pairs ----
  for (int iy=ty; iy<42; iy+=32){
    for (int xp=tx; xp<34; xp+=32){
      int x0=2*xp;
      int base=iy*76+x0;
      float a0=0.f,a1=0.f,a2=0.f, b0=0.f,b1=0.f,b2=0.f;
      #pragma unroll
      for (int k=0;k<8;k++){
        float q0=p0[base+k], q1=p1[base+k], q2=p2[base+k];
        if (k<7){ a0+=w[k]*q0;   a1+=w[k]*q1;   a2+=w[k]*q2; }
        if (k>0){ b0+=w[k-1]*q0; b1+=w[k-1]*q1; b2+=w[k-1]*q2; }
      }
      int o = iy*68+x0;
      t0[o]=a0; t1[o]=a1; t2[o]=a2;
      t0[o+1]=b0; t1[o+1]=b1; t2[o+1]=b2;
    }
  }
  __syncthreads();

  // ---- D: col blur + min eigenvalue, 18 y-pairs x 68 cols ----
  for (int i=tid; i<1224; i+=1024){
    int row=i/68, x=i-row*68;
    int iy=2*row;
    float a0=0.f,a1=0.f,a2=0.f, b0=0.f,b1=0.f,b2=0.f;
    #pragma unroll
    for (int k=0;k<8;k++){
      int o=(iy+k)*68+x;
      float q0=t0[o], q1=t1[o], q2=t2[o];
      if (k<7){ a0+=w[k]*q0;   a1+=w[k]*q1;   a2+=w[k]*q2; }
      if (k>0){ b0+=w[k-1]*q0; b1+=w[k-1]*q1; b2+=w[k-1]*q2; }
    }
    {
      float det=a0*a1-a2*a2, tr=a0+a1;
      float r0=0.5f*(tr - fsqrt_pos(fabsf(tr*tr - 4.0f*det)));
      int ry=ty0-2+iy, rx=tx0-2+x;
      resp[iy*68+x] = (ry>=0 && ry<HW && rx>=0 && rx<HW) ? r0 : NEG;
    }
    {
      float det=b0*b1-b2*b2, tr=b0+b1;
      float r1=0.5f*(tr - fsqrt_pos(fabsf(tr*tr - 4.0f*det)));
      int ry=ty0-1+iy, rx=tx0-2+x;
      resp[(iy+1)*68+x] = (ry>=0 && ry<HW && rx>=0 && rx<HW) ? r1 : NEG;
    }
  }
  __syncthreads();

  // ---- E0: row max of 5, 36 x 64 ----
  for (int iy=ty; iy<36; iy+=32){
    for (int ix=tx; ix<64; ix+=32){
      int base=iy*68+ix;
      rm[iy*64+ix] = fmaxf(fmaxf(fmaxf(resp[base],resp[base+1]),
                                 fmaxf(resp[base+2],resp[base+3])),resp[base+4]);
    }
  }
  __syncthreads();

  // ---- E1: col max of 5 -> NMS, 32 x 64 ----
  {
    const int oy=ty;
    #pragma unroll
    for (int t=0;t<2;t++){
      int ox = tx + 32*t;
      float v = resp[(oy+2)*68 + ox+2];
      float m = fmaxf(fmaxf(fmaxf(rm[oy*64+ox],rm[(oy+1)*64+ox]),
                            fmaxf(rm[(oy+2)*64+ox],rm[(oy+3)*64+ox])),rm[(oy+4)*64+ox]);
      sv[oy*64+ox] = (v==m) ? v : 0.0f;
    }
  }
  __syncthreads();

  // ---- E2: per-8x8-block max ----
  if (tid < 32){
    int by = tid>>3, bx = tid&7;
    int y0 = by*8, x0 = bx*8;
    float bv = sv[y0*64+x0];
    int   bp = (ty0+y0)*HW + (tx0+x0);
    for (int r=0;r<8;r++)
      for (int j=0;j<8;j++){
        float q = sv[(y0+r)*64 + x0+j];
        if (q > bv){ bv=q; bp=(ty0+y0+r)*HW + (tx0+x0+j); }
      }
    int bidx = b*4096 + ((ty0>>3)+by)*64 + (tx0>>3)+bx;
    g_bval[bidx]=bv; g_bpos[bidx]=bp;
  }

  // ---- per-image arrival; last CTA of this image runs the select phase ----
  __shared__ unsigned s_flag;
  __threadfence();
  __syncthreads();
  if (tid==0){
    unsigned t = atomicAdd(&g_imgarr[b], 1u);
    s_flag = (t == (unsigned)(CTAS_PER_IMG-1));
  }
  __syncthreads();
  if (!s_flag) return;

  // ======== K2 body: radix-select (500th) + second NMS + deterministic compaction ========
  const int img = b;
  float* fv  = buf;                   // 4096
  int*   pos = (int*)(buf + 4096);    // 4096
  unsigned* hist = (unsigned*)(buf + 8192);  // 256
  int* wsum = (int*)(buf + 8448);     // 32
  __shared__ unsigned s_prefix;
  __shared__ int s_k;

  for (int i=tid;i<4096;i+=1024){
    fv[i]=g_bval[img*4096+i];
    pos[i]=g_bpos[img*4096+i];
  }
  if (tid==0){ s_prefix=0u; s_k=500; g_imgarr[b]=0u; }
  __syncthreads();

  for (int pass=0; pass<4; pass++){
    int shift = 24 - 8*pass;
    unsigned hi_mask = (pass==0) ? 0u : (0xFFFFFFFFu << (shift+8));
    if (tid < 256) hist[tid]=0u;
    __syncthreads();
    unsigned pfx = s_prefix;
    int kk = s_k;
    for (int i=tid;i<4096;i+=1024){
      unsigned bits = __float_as_uint(fv[i]);
      unsigned u = (bits & 0x80000000u) ? ~bits : (bits | 0x80000000u);
      if ((u & hi_mask) == pfx) atomicAdd(&hist[(u>>shift)&255u], 1u);
    }
    __syncthreads();
    if (tid<32){
      int base=tid*8;
      unsigned c[8];
      #pragma unroll
      for (int j=0;j<8;j++) c[j]=hist[base+j];
      unsigned tot=0;
      #pragma unroll
      for (int j=0;j<8;j++) tot+=c[j];
      unsigned suf=tot;
      #pragma unroll
      for (int off=1;off<32;off<<=1){
        unsigned n=__shfl_down_sync(0xffffffffu, suf, off);
        if (lane+off<32) suf+=n;
      }
      unsigned run = suf - tot;
      #pragma unroll
      for (int j=7;j>=0;j--){ run += c[j]; hist[base+j]=run; }
    }
    __syncthreads();
    if (tid<256){
      unsigned ge = hist[tid];
      unsigned gt = (tid<255) ? hist[tid+1] : 0u;
      if (ge >= (unsigned)kk && gt < (unsigned)kk){
        s_prefix = pfx | ((unsigned)tid << shift);
        s_k = kk - (int)gt;
      }
    }
    __syncthreads();
  }
  unsigned u = s_prefix;
  unsigned tbits = (u & 0x80000000u) ? (u ^ 0x80000000u) : ~u;
  float thr = __uint_as_float(tbits);

  int srv[4];
  int mycnt = 0;
  #pragma unroll
  for (int j=0;j<4;j++){
    int i = tid*4 + j;
    float v = fv[i];
    int s = -1;
    if (v>0.0f && v>=thr){
      int by=i>>6, bx=i&63;
      int p = pos[i];
      int y=p>>9, x=p&511;
      bool ok = true;
      #pragma unroll
      for (int dby=-1;dby<=1;dby++)
        #pragma unroll
        for (int dbx=-1;dbx<=1;dbx++){
          if (dby==0 && dbx==0) continue;
          int nby=by+dby, nbx=bx+dbx;
          if (nby<0||nby>63||nbx<0||nbx>63) continue;
          int n = nby*64+nbx;
          float nv = fv[n];
          if (nv>v && nv>=thr){
            int np = pos[n];
            int ny=np>>9, nx=np&511;
            if (abs(ny-y)<=2 && abs(nx-x)<=2) ok=false;
          }
        }
      s = ok ? p : -1;
    }
    srv[j]=s;
    mycnt += (s>=0);
  }
  int v = mycnt;
  #pragma unroll
  for (int off=1;off<32;off<<=1){
    int n=__shfl_up_sync(0xffffffffu, v, off);
    if (lane>=off) v+=n;
  }
  if (lane==31) wsum[wrp]=v;
  __syncthreads();
  if (wrp==0){
    int s=wsum[lane];
    #pragma unroll
    for (int off=1;off<32;off<<=1){
      int n=__shfl_up_sync(0xffffffffu, s, off);
      if (lane>=off) s+=n;
    }
    wsum[lane]=s;
  }
  __syncthreads();
  int offs = (wrp ? wsum[wrp-1] : 0) + v - mycnt;
  #pragma unroll
  for (int j=0;j<4;j++){
    if (srv[j]>=0){
      if (offs < LCAP) g_list[img*LCAP + offs] = srv[j];
      offs++;
    }
  }
  if (tid==1023){
    int tot = wsum[31];
    g_cnt[img] = tot > LCAP ? LCAP : tot;
  }
}

// ============ K4: warp-per-survivor correction + fused final reduction ============
__global__ __launch_bounds__(1024) void k4(const float* __restrict__ scores,
                                           float* __restrict__ out){
  const int tid = threadIdx.x;
  const int wid = tid>>5, lane = tid&31;
  const int w32 = blockIdx.x*32 + wid;
  const int img = w32 / LCAP;
  const int idx = w32 - img*LCAP;
  __shared__ float wsumf[32];
  __shared__ bool isLast;
  float acc = 0.0f;
  if (idx < g_cnt[img]){
    const int s = g_list[w32];
    const float* sp = scores + (size_t)img*HW*HW;
    float wk[7]; gw7(wk);
    const int y = s>>9, x = s&511;
    #pragma unroll
    for (int t=lane; t<49; t+=32){
      int ky=t/7, kx=t-ky*7;
      int yy = refl512(y+ky-3);
      int xx = refl512(x+kx-3);
      float p = sp[yy*HW+xx];
      float lp = fmaxf(__logf(p), -100.0f);
      float l1 = fmaxf(__logf(1.0f-p), -100.0f);
      acc += wk[ky]*wk[kx]*(lp - l1);
    }
  }
  #pragma unroll
  for (int off=16;off;off>>=1) acc += __shfl_down_sync(0xffffffffu, acc, off);
  if (lane==0) wsumf[wid]=acc;
  __syncthreads();
  if (tid==0){
    double s=0.0;
    for (int i=0;i<32;i++) s += (double)wsumf[i];
    g_pc[blockIdx.x]=s;
    __threadfence();
    unsigned t = atomicAdd(&g_arrive, 1u);
    isLast = (t == (unsigned)(gridDim.x-1));
  }
  __syncthreads();
  if (!isLast) return;

  __shared__ double sb[1024], sr[1024], sx[1024];
  double bsum=0.0, rsum=0.0;
  for (int i=tid;i<NPART;i+=1024){ bsum += g_pb[i]; rsum += g_pr[i]; }
  double csum = (tid<K4CTAS) ? g_pc[tid] : 0.0;
  sb[tid]=bsum; sr[tid]=rsum; sx[tid]=csum;
  __syncthreads();
  for (int s=512;s;s>>=1){
    if (tid<s){ sb[tid]+=sb[tid+s]; sr[tid]+=sr[tid+s]; sx[tid]+=sx[tid+s]; }
    __syncthreads();
  }
  if (tid==0){
    double n = (double)NPIX;
    out[0] = (float)((sb[0]-sx[0])/n + (sr[0]/n)*10.0);
    g_arrive = 0u;
  }
}

// ---------------- launch ----------------
extern "C" void kernel_launch(void* const* d_in, const int* in_sizes, int n_in,
                              void* d_out, int out_size){
  const float* scores = (const float*)d_in[0];
  const float* imgs   = (const float*)d_in[1];
  if (in_sizes[0] != NB*1*HW*HW){
    const float* tmp = scores; scores = imgs; imgs = tmp;
  }
  const int smem_bytes = BUFSZ*4;  // 105216
  static int configured = 0;
  if (!configured){
    cudaFuncSetAttribute(kmain, cudaFuncAttributeMaxDynamicSharedMemorySize, smem_bytes);
    configured = 1;
  }
  dim3 blk(32,32);
  dim3 grd(8,16,NB);
  kmain<<<grd, blk, smem_bytes>>>(imgs, scores);
  k4<<<K4CTAS, 1024>>>(scores, (float*)d_out);
}